// round 12
// baseline (speedup 1.0000x reference)
#include <cuda_runtime.h>
#include <cuda_bf16.h>
#include <cstdint>

typedef unsigned int u32t;

#define BNUM 1024
#define QNUM 96
#define CNUM 16
#define HNUM 100
#define NSTEPS_K 100
#define QP1 97
#define ROWS (BNUM*CNUM)
#define MT 112
#define GRID 147
#define NTHREADS 256      // 8 warps: p=w&3 (pair), sub=w>>2 (tile half)

#define SWB 208           // row stride bytes (104 bf16) = 52 words, conflict-free
#define NTW 7             // tiles per warp (ntb = 6*sub; tile 6 duplicated)
#define ROW8 (8*SWB)      // 1664

// SMEM: A[pp][hl]: 4 buffers x 112 rows; W; bias
#define ABUF  (112*SWB)              // 23296
#define OFF_A 0
#define OFF_W (4*ABUF)               // 93184
#define WBUF  (104*SWB)              // 21632 (W1hi W1lo W2hi W2lo W3hi W3lo)
#define OFF_BIAS (OFF_W + 6*WBUF)    // 222976
#define SMEM_TOTAL (OFF_BIAS + 3*104*4 + 64)  // 224288

extern __shared__ char smbase[];

__device__ __forceinline__ u32t smem_u32(const void* p) {
    u32t a;
    asm("{ .reg .u64 t; cvta.to.shared.u64 t, %1; cvt.u32.u64 %0, t; }" : "=r"(a) : "l"(p));
    return a;
}
__device__ __forceinline__ float tanh_fast(float x) {
    asm("tanh.approx.f32 %0, %0;" : "+f"(x));
    return x;
}
__device__ __forceinline__ u32t ldsw(u32t a) {
    u32t v; asm("ld.shared.b32 %0, [%1];" : "=r"(v) : "r"(a)); return v;
}
__device__ __forceinline__ float ldsf(u32t a) {
    float v; asm("ld.shared.f32 %0, [%1];" : "=f"(v) : "r"(a)); return v;
}
__device__ __forceinline__ void stsw(u32t a, u32t v) {
    asm volatile("st.shared.b32 [%0], %1;" :: "r"(a), "r"(v));
}
__device__ __forceinline__ void split2(float v0, float v1, u32t& hi, u32t& lo) {
    asm("cvt.rn.bf16x2.f32 %0, %1, %2;" : "=r"(hi) : "f"(v1), "f"(v0));
    float h0 = __uint_as_float(hi << 16);
    float h1 = __uint_as_float(hi & 0xFFFF0000u);
    float l0 = v0 - h0, l1 = v1 - h1;
    asm("cvt.rn.bf16x2.f32 %0, %1, %2;" : "=r"(lo) : "f"(l1), "f"(l0));
}
__device__ __forceinline__ void mma16(float (&d)[4], u32t a0, u32t a1, u32t a2, u32t a3,
                                      u32t b0, u32t b1) {
    asm volatile("mma.sync.aligned.m16n8k16.row.col.f32.bf16.bf16.f32 "
        "{%0,%1,%2,%3}, {%4,%5,%6,%7}, {%8,%9}, {%0,%1,%2,%3};"
        : "+f"(d[0]), "+f"(d[1]), "+f"(d[2]), "+f"(d[3])
        : "r"(a0), "r"(a1), "r"(a2), "r"(a3), "r"(b0), "r"(b1));
}
__device__ __forceinline__ void mma8(float (&d)[4], u32t a0, u32t a1, u32t b0) {
    asm volatile("mma.sync.aligned.m16n8k8.row.col.f32.bf16.bf16.f32 "
        "{%0,%1,%2,%3}, {%4,%5}, {%6}, {%0,%1,%2,%3};"
        : "+f"(d[0]), "+f"(d[1]), "+f"(d[2]), "+f"(d[3])
        : "r"(a0), "r"(a1), "r"(b0));
}

__global__ __launch_bounds__(NTHREADS, 1)
void arima_mma_kernel(const float* __restrict__ series,
                      const float* __restrict__ rand_error,
                      const float* __restrict__ W1, const float* __restrict__ b1,
                      const float* __restrict__ W2, const float* __restrict__ b2,
                      const float* __restrict__ W3, const float* __restrict__ b3,
                      float* __restrict__ out)
{
    const u32t sb = smem_u32(smbase);
    const int tid  = threadIdx.x;
    const int w    = tid >> 5;
    const int lane = tid & 31;
    const int l4   = lane & 3;
    const int lr   = lane >> 2;
    const int p    = w & 3;          // pair id (slab group)
    const int sub  = w >> 2;         // tile half
    const int ns   = (p < 3) ? 2 : 1;
    const int ntb  = sub * 6;
    const int base = blockIdx.x * MT;
    const float dt = 1.0f / (float)NSTEPS_K;

    #define PBAR() asm volatile("bar.sync %0, %1;" :: "r"(p + 1), "r"(64) : "memory")

    // slab rows: pair p<3 -> slabs 2p,2p+1 ; pair 3 -> slab 6
    int r0a[2];
    r0a[0] = ((p < 3) ? 2 * p : 6) * 16 + lr;
    r0a[1] = r0a[0] + 16;   // only valid when ns==2

    // ---- zero smem ----
    for (int i = tid; i < SMEM_TOTAL / 4; i += NTHREADS)
        ((u32t*)smbase)[i] = 0u;
    __syncthreads();

    // ---- weights -> SMEM bf16 hi/lo, row-major [j][k], stride 104 ----
    char* Wp = smbase + OFF_W;
    for (int idx = tid; idx < HNUM * (QNUM + 2); idx += NTHREADS) {
        int j = idx / (QNUM + 2), k = idx - j * (QNUM + 2);
        float v = W1[idx];
        __nv_bfloat16 h = __float2bfloat16(v);
        __nv_bfloat16 l = __float2bfloat16(v - __bfloat162float(h));
        u32t o = (u32t)(j * SWB + k * 2);
        *(__nv_bfloat16*)(Wp + 0 * WBUF + o) = h;
        *(__nv_bfloat16*)(Wp + 1 * WBUF + o) = l;
    }
    for (int idx = tid; idx < HNUM * HNUM; idx += NTHREADS) {
        int j = idx / HNUM, k = idx - j * HNUM;
        float v = W2[idx];
        __nv_bfloat16 h = __float2bfloat16(v);
        __nv_bfloat16 l = __float2bfloat16(v - __bfloat162float(h));
        u32t o = (u32t)(j * SWB + k * 2);
        *(__nv_bfloat16*)(Wp + 2 * WBUF + o) = h;
        *(__nv_bfloat16*)(Wp + 3 * WBUF + o) = l;
    }
    for (int idx = tid; idx < QP1 * HNUM; idx += NTHREADS) {
        int j = idx / HNUM, k = idx - j * HNUM;
        float v = W3[idx];
        __nv_bfloat16 h = __float2bfloat16(v);
        __nv_bfloat16 l = __float2bfloat16(v - __bfloat162float(h));
        u32t o = (u32t)(j * SWB + k * 2);
        *(__nv_bfloat16*)(Wp + 4 * WBUF + o) = h;
        *(__nv_bfloat16*)(Wp + 5 * WBUF + o) = l;
    }
    float* biasp = (float*)(smbase + OFF_BIAS);
    for (int j = tid; j < HNUM; j += NTHREADS) {
        biasp[j]       = b1[j];
        biasp[104 + j] = b2[j];
    }
    for (int j = tid; j < QP1; j += NTHREADS) biasp[208 + j] = b3[j];

    // ---- per-slab global row helpers ----
    bool gv0[2], gv1[2];
    int gb0[2], gc0[2], gb1[2], gc1[2];
    const float *ps0[2], *ps1[2], *pr0[2], *pr1[2];
    #pragma unroll
    for (int j = 0; j < 2; j++) {
        int g0 = base + r0a[j], g1 = g0 + 8;
        gv0[j] = (j < ns) && (g0 < ROWS);
        gv1[j] = (j < ns) && (g1 < ROWS);
        gb0[j] = g0 >> 4; gc0[j] = g0 & 15;
        gb1[j] = g1 >> 4; gc1[j] = g1 & 15;
        ps0[j] = series + (size_t)gb0[j] * (QNUM * CNUM) + gc0[j];
        ps1[j] = series + (size_t)gb1[j] * (QNUM * CNUM) + gc1[j];
        pr0[j] = rand_error + (size_t)gb0[j] * CNUM + gc0[j];
        pr1[j] = rand_error + (size_t)gb1[j] * CNUM + gc1[j];
    }

    // ---- x0 into D-fragment registers ----
    float x[2][NTW][4];
    #pragma unroll
    for (int j = 0; j < 2; j++)
        #pragma unroll
        for (int n = 0; n < NTW; n++) {
            int q0 = (ntb + n) * 8 + l4 * 2, q1 = q0 + 1;
            x[j][n][0] = (gv0[j] && q0 < QNUM) ? __ldg(ps0[j] + q0 * CNUM) : (gv0[j] && q0 == QNUM) ? __ldg(pr0[j]) : 0.0f;
            x[j][n][1] = (gv0[j] && q1 < QNUM) ? __ldg(ps0[j] + q1 * CNUM) : (gv0[j] && q1 == QNUM) ? __ldg(pr0[j]) : 0.0f;
            x[j][n][2] = (gv1[j] && q0 < QNUM) ? __ldg(ps1[j] + q0 * CNUM) : (gv1[j] && q0 == QNUM) ? __ldg(pr1[j]) : 0.0f;
            x[j][n][3] = (gv1[j] && q1 < QNUM) ? __ldg(ps1[j] + q1 * CNUM) : (gv1[j] && q1 == QNUM) ? __ldg(pr1[j]) : 0.0f;
        }

    const bool tinj = (sub == 1) && (l4 == 0);
    u32t abw[2];
    abw[0] = (u32t)(r0a[0] * SWB + l4 * 4);
    abw[1] = (u32t)(r0a[1] * SWB + l4 * 4);

    // store x -> A buffer `pp` (hi/lo), t injected at col 97
    auto store_xA = [&](int pp, float tn) {
        u32t wb = sb + OFF_A + (u32t)pp * (2 * ABUF);
        #pragma unroll
        for (int j = 0; j < 2; j++) {
            if (j >= ns) break;
            #pragma unroll
            for (int n = 0; n < NTW; n++) {
                float v0 = x[j][n][0], v1 = x[j][n][1], v2 = x[j][n][2], v3 = x[j][n][3];
                if (n == 6 && tinj) { v1 = tn; v3 = tn; }
                u32t bo = wb + abw[j] + (u32t)((ntb + n) * 16);
                u32t hw, lw;
                split2(v0, v1, hw, lw);
                stsw(bo, hw);
                stsw(bo + ABUF, lw);
                split2(v2, v3, hw, lw);
                stsw(bo + ROW8, hw);
                stsw(bo + ROW8 + ABUF, lw);
            }
        }
    };
    store_xA(0, 0.0f);
    __syncthreads();  // weights + initial A visible

    const u32t wJ = (u32t)(lr * SWB + l4 * 4);
    int pp = 0;

    for (int s = 0; s < NSTEPS_K; s++) {
        #pragma unroll 1
        for (int l = 0; l < 3; l++) {
            float acc[2][NTW][4];
            #pragma unroll
            for (int j = 0; j < 2; j++)
                #pragma unroll
                for (int n = 0; n < NTW; n++)
                    #pragma unroll
                    for (int e = 0; e < 4; e++) acc[j][n][e] = 0.0f;

            const u32t ab  = sb + OFF_A + (u32t)pp * (2 * ABUF);
            const u32t wHb = sb + OFF_W + (u32t)l * (2 * WBUF) + wJ + (u32t)(ntb * ROW8);
            const u32t wLb = wHb + WBUF;

            #pragma unroll 1
            for (int kc = 0; kc < 6; kc++) {
                u32t ko = (u32t)(kc * 32);
                u32t h[2][4], g[2][4];
                #pragma unroll
                for (int j = 0; j < 2; j++) {
                    if (j >= ns) break;
                    u32t a0 = ab + abw[j] + ko;
                    h[j][0] = ldsw(a0);            h[j][1] = ldsw(a0 + ROW8);
                    h[j][2] = ldsw(a0 + 16);       h[j][3] = ldsw(a0 + ROW8 + 16);
                    g[j][0] = ldsw(a0 + ABUF);     g[j][1] = ldsw(a0 + ABUF + ROW8);
                    g[j][2] = ldsw(a0 + ABUF + 16);g[j][3] = ldsw(a0 + ABUF + ROW8 + 16);
                }
                #pragma unroll
                for (int n = 0; n < NTW; n++) {
                    u32t wo = ko + (u32t)(n * ROW8);
                    u32t bh0 = ldsw(wHb + wo), bh1 = ldsw(wHb + wo + 16);
                    u32t bl0 = ldsw(wLb + wo), bl1 = ldsw(wLb + wo + 16);
                    #pragma unroll
                    for (int j = 0; j < 2; j++) {
                        if (j >= ns) break;
                        mma16(acc[j][n], h[j][0], h[j][1], h[j][2], h[j][3], bh0, bh1);
                        mma16(acc[j][n], h[j][0], h[j][1], h[j][2], h[j][3], bl0, bl1);
                        mma16(acc[j][n], g[j][0], g[j][1], g[j][2], g[j][3], bh0, bh1);
                    }
                }
            }
            {   // k8 tail: k = 96..103
                u32t ko = 192;
                u32t h[2][2], g[2][2];
                #pragma unroll
                for (int j = 0; j < 2; j++) {
                    if (j >= ns) break;
                    u32t a0 = ab + abw[j] + ko;
                    h[j][0] = ldsw(a0);        h[j][1] = ldsw(a0 + ROW8);
                    g[j][0] = ldsw(a0 + ABUF); g[j][1] = ldsw(a0 + ABUF + ROW8);
                }
                #pragma unroll
                for (int n = 0; n < NTW; n++) {
                    u32t wo = ko + (u32t)(n * ROW8);
                    u32t bh0 = ldsw(wHb + wo);
                    u32t bl0 = ldsw(wLb + wo);
                    #pragma unroll
                    for (int j = 0; j < 2; j++) {
                        if (j >= ns) break;
                        mma8(acc[j][n], h[j][0], h[j][1], bh0);
                        mma8(acc[j][n], h[j][0], h[j][1], bl0);
                        mma8(acc[j][n], g[j][0], g[j][1], bh0);
                    }
                }
            }

            // epilogue writes the OTHER buffer -> no pre-epilogue barrier needed
            const u32t wb = sb + OFF_A + (u32t)(pp ^ 1) * (2 * ABUF);

            if (l < 2) {
                // ===== hidden epilogue: A' <- tanh(acc + bias) =====
                const u32t bp = sb + OFF_BIAS + (u32t)(l * 416 + ntb * 32 + l4 * 8);
                #pragma unroll
                for (int j = 0; j < 2; j++) {
                    if (j >= ns) break;
                    #pragma unroll
                    for (int n = 0; n < NTW; n++) {
                        float bb0 = ldsf(bp + (u32t)(n * 32));
                        float bb1 = ldsf(bp + (u32t)(n * 32) + 4);
                        float v0 = tanh_fast(acc[j][n][0] + bb0);
                        float v1 = tanh_fast(acc[j][n][1] + bb1);
                        float v2 = tanh_fast(acc[j][n][2] + bb0);
                        float v3 = tanh_fast(acc[j][n][3] + bb1);
                        u32t bo = wb + abw[j] + (u32t)((ntb + n) * 16);
                        u32t hw, lw;
                        split2(v0, v1, hw, lw);
                        stsw(bo, hw);
                        stsw(bo + ABUF, lw);
                        split2(v2, v3, hw, lw);
                        stsw(bo + ROW8, hw);
                        stsw(bo + ROW8 + ABUF, lw);
                    }
                }
            } else {
                // ===== Euler epilogue: x += (acc + b3 - noise)*dt; A' <- x, t_next =====
                const u32t bp3 = sb + OFF_BIAS + (u32t)(2 * 416 + ntb * 32 + l4 * 8);
                #pragma unroll
                for (int j = 0; j < 2; j++) {
                    if (j >= ns) break;
                    #pragma unroll
                    for (int n = 0; n < NTW; n++) {
                        int nt = ntb + n;
                        float bb0 = ldsf(bp3 + (u32t)(n * 32));
                        float bb1 = ldsf(bp3 + (u32t)(n * 32) + 4);
                        float nz0, nz1, nz2, nz3;
                        if (nt < 12) {
                            int q0 = nt * 8 + l4 * 2, q1 = q0 + 1;   // < 96
                            nz0 = gv0[j] ? __ldg(ps0[j] + q0 * CNUM) : 0.0f;
                            nz1 = gv0[j] ? __ldg(ps0[j] + q1 * CNUM) : 0.0f;
                            nz2 = gv1[j] ? __ldg(ps1[j] + q0 * CNUM) : 0.0f;
                            nz3 = gv1[j] ? __ldg(ps1[j] + q1 * CNUM) : 0.0f;
                        } else {
                            nz0 = (l4 == 0 && gv0[j]) ? __ldg(pr0[j]) : 0.0f;  // col 96
                            nz1 = 0.0f;
                            nz2 = (l4 == 0 && gv1[j]) ? __ldg(pr1[j]) : 0.0f;
                            nz3 = 0.0f;
                        }
                        x[j][n][0] = fmaf((acc[j][n][0] + bb0) - nz0, dt, x[j][n][0]);
                        x[j][n][1] = fmaf((acc[j][n][1] + bb1) - nz1, dt, x[j][n][1]);
                        x[j][n][2] = fmaf((acc[j][n][2] + bb0) - nz2, dt, x[j][n][2]);
                        x[j][n][3] = fmaf((acc[j][n][3] + bb1) - nz3, dt, x[j][n][3]);
                    }
                }
                store_xA(pp ^ 1, (float)(s + 1) * dt);
            }
            PBAR();     // pair's epilogue stores visible before next layer reads
            pp ^= 1;
        }
    }

    // ---- write result (B, 97, C) from x registers ----
    #pragma unroll
    for (int j = 0; j < 2; j++) {
        if (j >= ns) break;
        #pragma unroll
        for (int n = 0; n < NTW; n++) {
            int q0 = (ntb + n) * 8 + l4 * 2, q1 = q0 + 1;
            if (gv0[j] && q0 < QP1) out[((size_t)gb0[j] * QP1 + q0) * CNUM + gc0[j]] = x[j][n][0];
            if (gv0[j] && q1 < QP1) out[((size_t)gb0[j] * QP1 + q1) * CNUM + gc0[j]] = x[j][n][1];
            if (gv1[j] && q0 < QP1) out[((size_t)gb1[j] * QP1 + q0) * CNUM + gc1[j]] = x[j][n][2];
            if (gv1[j] && q1 < QP1) out[((size_t)gb1[j] * QP1 + q1) * CNUM + gc1[j]] = x[j][n][3];
        }
    }
    #undef PBAR
}

extern "C" void kernel_launch(void* const* d_in, const int* in_sizes, int n_in,
                              void* d_out, int out_size)
{
    const float* series     = (const float*)d_in[0];
    const float* rand_error = (const float*)d_in[1];
    const float* W1 = (const float*)d_in[2];
    const float* b1 = (const float*)d_in[3];
    const float* W2 = (const float*)d_in[4];
    const float* b2 = (const float*)d_in[5];
    const float* W3 = (const float*)d_in[6];
    const float* b3 = (const float*)d_in[7];
    float* out = (float*)d_out;

    cudaFuncSetAttribute(arima_mma_kernel,
                         cudaFuncAttributeMaxDynamicSharedMemorySize, SMEM_TOTAL);
    arima_mma_kernel<<<GRID, NTHREADS, SMEM_TOTAL>>>(
        series, rand_error, W1, b1, W2, b2, W3, b3, out);
}

// round 14
// speedup vs baseline: 1.3937x; 1.3937x over previous
#include <cuda_runtime.h>
#include <cuda_bf16.h>
#include <cstdint>

typedef unsigned int u32t;

#define BNUM 1024
#define QNUM 96
#define CNUM 16
#define HNUM 100
#define NSTEPS_K 100
#define QP1 97
#define ROWS (BNUM*CNUM)
#define MT 112
#define GRID 147
#define NTHREADS 224      // 7 warps, warp w owns rows w*16..w*16+15
#define NT 13             // n8 tiles per warp (full width)

#define SWB 208           // W row stride bytes (104 bf16) = 52 words, conflict-free
#define ROW8 (8*SWB)      // 1664

// SMEM: W (bf16 hi/lo) + bias + x state (fp32)
#define WBUF  (104*SWB)              // 21632 (W1hi W1lo W2hi W2lo W3hi W3lo)
#define OFF_W 0
#define OFF_BIAS (6*WBUF)            // 129792 ; bias[l][104] fp32
#define OFF_X    (OFF_BIAS + 1280)   // 131072
#define XSTR  106                    // floats per x row (EVEN -> v2.f32 aligned)
#define SMEM_TOTAL (OFF_X + 112*XSTR*4)   // 178560

extern __shared__ char smbase[];

__device__ __forceinline__ u32t smem_u32(const void* p) {
    u32t a;
    asm("{ .reg .u64 t; cvta.to.shared.u64 t, %1; cvt.u32.u64 %0, t; }" : "=r"(a) : "l"(p));
    return a;
}
__device__ __forceinline__ float tanh_fast(float x) {
    asm("tanh.approx.f32 %0, %0;" : "+f"(x));
    return x;
}
__device__ __forceinline__ u32t ldsw(u32t a) {
    u32t v; asm("ld.shared.b32 %0, [%1];" : "=r"(v) : "r"(a)); return v;
}
__device__ __forceinline__ float ldsf(u32t a) {
    float v; asm("ld.shared.f32 %0, [%1];" : "=f"(v) : "r"(a)); return v;
}
__device__ __forceinline__ void lds64(u32t a, float& x, float& y) {
    asm("ld.shared.v2.f32 {%0, %1}, [%2];" : "=f"(x), "=f"(y) : "r"(a));
}
__device__ __forceinline__ void sts64(u32t a, float x, float y) {
    asm volatile("st.shared.v2.f32 [%0], {%1, %2};" :: "r"(a), "f"(x), "f"(y));
}
// pack (v0 -> low bf16, v1 -> high bf16) plus bf16 residual pair
__device__ __forceinline__ void split2(float v0, float v1, u32t& hi, u32t& lo) {
    asm("cvt.rn.bf16x2.f32 %0, %1, %2;" : "=r"(hi) : "f"(v1), "f"(v0));
    float h0 = __uint_as_float(hi << 16);
    float h1 = __uint_as_float(hi & 0xFFFF0000u);
    float l0 = v0 - h0, l1 = v1 - h1;
    asm("cvt.rn.bf16x2.f32 %0, %1, %2;" : "=r"(lo) : "f"(l1), "f"(l0));
}
__device__ __forceinline__ void mma16(float (&d)[4], u32t a0, u32t a1, u32t a2, u32t a3,
                                      u32t b0, u32t b1) {
    asm volatile("mma.sync.aligned.m16n8k16.row.col.f32.bf16.bf16.f32 "
        "{%0,%1,%2,%3}, {%4,%5,%6,%7}, {%8,%9}, {%0,%1,%2,%3};"
        : "+f"(d[0]), "+f"(d[1]), "+f"(d[2]), "+f"(d[3])
        : "r"(a0), "r"(a1), "r"(a2), "r"(a3), "r"(b0), "r"(b1));
}
__device__ __forceinline__ void mma8(float (&d)[4], u32t a0, u32t a1, u32t b0) {
    asm volatile("mma.sync.aligned.m16n8k8.row.col.f32.bf16.bf16.f32 "
        "{%0,%1,%2,%3}, {%4,%5}, {%6}, {%0,%1,%2,%3};"
        : "+f"(d[0]), "+f"(d[1]), "+f"(d[2]), "+f"(d[3])
        : "r"(a0), "r"(a1), "r"(b0));
}

__global__ __launch_bounds__(NTHREADS, 1)
void arima_mma_kernel(const float* __restrict__ series,
                      const float* __restrict__ rand_error,
                      const float* __restrict__ W1, const float* __restrict__ b1,
                      const float* __restrict__ W2, const float* __restrict__ b2,
                      const float* __restrict__ W3, const float* __restrict__ b3,
                      float* __restrict__ out)
{
    const u32t sb = smem_u32(smbase);
    const int tid  = threadIdx.x;
    const int w    = tid >> 5;
    const int lane = tid & 31;
    const int l4   = lane & 3;
    const int lr   = lane >> 2;
    const int base = blockIdx.x * MT;
    const int r0   = w * 16 + lr;    // fragment row (0..111)
    const float dt = 1.0f / (float)NSTEPS_K;

    // ---- zero smem ----
    for (int i = tid; i < SMEM_TOTAL / 4; i += NTHREADS)
        ((u32t*)smbase)[i] = 0u;
    __syncthreads();

    // ---- weights -> SMEM bf16 hi/lo, row-major [j][k], stride 104 ----
    char* Wp = smbase + OFF_W;
    for (int idx = tid; idx < HNUM * (QNUM + 2); idx += NTHREADS) {
        int j = idx / (QNUM + 2), k = idx - j * (QNUM + 2);
        float v = W1[idx];
        __nv_bfloat16 h = __float2bfloat16(v);
        __nv_bfloat16 l = __float2bfloat16(v - __bfloat162float(h));
        u32t o = (u32t)(j * SWB + k * 2);
        *(__nv_bfloat16*)(Wp + 0 * WBUF + o) = h;
        *(__nv_bfloat16*)(Wp + 1 * WBUF + o) = l;
    }
    for (int idx = tid; idx < HNUM * HNUM; idx += NTHREADS) {
        int j = idx / HNUM, k = idx - j * HNUM;
        float v = W2[idx];
        __nv_bfloat16 h = __float2bfloat16(v);
        __nv_bfloat16 l = __float2bfloat16(v - __bfloat162float(h));
        u32t o = (u32t)(j * SWB + k * 2);
        *(__nv_bfloat16*)(Wp + 2 * WBUF + o) = h;
        *(__nv_bfloat16*)(Wp + 3 * WBUF + o) = l;
    }
    for (int idx = tid; idx < QP1 * HNUM; idx += NTHREADS) {
        int j = idx / HNUM, k = idx - j * HNUM;
        float v = W3[idx];
        __nv_bfloat16 h = __float2bfloat16(v);
        __nv_bfloat16 l = __float2bfloat16(v - __bfloat162float(h));
        u32t o = (u32t)(j * SWB + k * 2);
        *(__nv_bfloat16*)(Wp + 4 * WBUF + o) = h;
        *(__nv_bfloat16*)(Wp + 5 * WBUF + o) = l;
    }
    float* biasp = (float*)(smbase + OFF_BIAS);
    for (int j = tid; j < HNUM; j += NTHREADS) {
        biasp[j]       = b1[j];
        biasp[104 + j] = b2[j];
    }
    for (int j = tid; j < QP1; j += NTHREADS) biasp[208 + j] = b3[j];

    // ---- per-thread global row helpers ----
    const int grow0 = base + r0, grow1 = grow0 + 8;
    const bool gv0 = grow0 < ROWS, gv1 = grow1 < ROWS;
    const int gb0 = grow0 >> 4, gc0 = grow0 & 15;
    const int gb1 = grow1 >> 4, gc1 = grow1 & 15;
    const float* ps0 = series + (size_t)gb0 * (QNUM * CNUM) + gc0;
    const float* ps1 = series + (size_t)gb1 * (QNUM * CNUM) + gc1;
    const float* pr0 = rand_error + (size_t)gb0 * CNUM + gc0;
    const float* pr1 = rand_error + (size_t)gb1 * CNUM + gc1;

    // x smem addresses for this thread's fragment positions (8B aligned: XSTR even)
    const u32t xb0 = sb + OFF_X + (u32t)(r0 * XSTR + l4 * 2) * 4;        // row r0
    const u32t xb1 = sb + OFF_X + (u32t)((r0 + 8) * XSTR + l4 * 2) * 4;  // row r0+8

    // ---- A fragments live in registers: aH/aL[kc][frag] (kc=6 uses [0..1]) ----
    u32t aH[7][4], aL[7][4];

    // ---- init: load x0, store to x smem, build initial A fragments (t=0) ----
    #pragma unroll
    for (int n = 0; n < NT; n++) {
        int q0 = n * 8 + l4 * 2, q1 = q0 + 1;
        float v0 = (gv0 && q0 < QNUM) ? __ldg(ps0 + q0 * CNUM) : (gv0 && q0 == QNUM) ? __ldg(pr0) : 0.0f;
        float v1 = (gv0 && q1 < QNUM) ? __ldg(ps0 + q1 * CNUM) : 0.0f;
        float v2 = (gv1 && q0 < QNUM) ? __ldg(ps1 + q0 * CNUM) : (gv1 && q0 == QNUM) ? __ldg(pr1) : 0.0f;
        float v3 = (gv1 && q1 < QNUM) ? __ldg(ps1 + q1 * CNUM) : 0.0f;
        sts64(xb0 + (u32t)(n * 32), v0, v1);   // x state (col 97 slot unused)
        sts64(xb1 + (u32t)(n * 32), v2, v3);
        // A fragment: col 97 = t (=0 at step 0); cols>=98 zero (already)
        int kc = n >> 1, f = (n & 1) * 2;
        split2(v0, v1, aH[kc][f],     aL[kc][f]);
        split2(v2, v3, aH[kc][f + 1], aL[kc][f + 1]);
    }
    __syncthreads();  // weights visible (x/A are warp-private)

    const u32t wJ = (u32t)(lr * SWB + l4 * 4);

    for (int s = 0; s < NSTEPS_K; s++) {
        #pragma unroll 1
        for (int l = 0; l < 3; l++) {
            float acc[NT][4];
            #pragma unroll
            for (int n = 0; n < NT; n++)
                #pragma unroll
                for (int e = 0; e < 4; e++) acc[n][e] = 0.0f;

            const u32t wHb = sb + OFF_W + (u32t)l * (2 * WBUF) + wJ;
            const u32t wLb = wHb + WBUF;

            #pragma unroll
            for (int kc = 0; kc < 6; kc++) {
                u32t ko = (u32t)(kc * 32);
                #pragma unroll
                for (int n = 0; n < NT; n++) {
                    u32t wo = ko + (u32t)(n * ROW8);
                    u32t bh0 = ldsw(wHb + wo), bh1 = ldsw(wHb + wo + 16);
                    u32t bl0 = ldsw(wLb + wo), bl1 = ldsw(wLb + wo + 16);
                    mma16(acc[n], aH[kc][0], aH[kc][1], aH[kc][2], aH[kc][3], bh0, bh1);
                    mma16(acc[n], aH[kc][0], aH[kc][1], aH[kc][2], aH[kc][3], bl0, bl1);
                    mma16(acc[n], aL[kc][0], aL[kc][1], aL[kc][2], aL[kc][3], bh0, bh1);
                }
            }
            {   // k8 tail: k = 96..103
                u32t ko = 192;
                #pragma unroll
                for (int n = 0; n < NT; n++) {
                    u32t wo = ko + (u32t)(n * ROW8);
                    u32t bh0 = ldsw(wHb + wo);
                    u32t bl0 = ldsw(wLb + wo);
                    mma8(acc[n], aH[6][0], aH[6][1], bh0);
                    mma8(acc[n], aH[6][0], aH[6][1], bl0);
                    mma8(acc[n], aL[6][0], aL[6][1], bh0);
                }
            }

            if (l < 2) {
                // ===== hidden epilogue: A <- tanh(acc + bias), in registers =====
                const u32t bp = sb + OFF_BIAS + (u32t)(l * 416 + l4 * 8);
                #pragma unroll
                for (int n = 0; n < NT; n++) {
                    float bb0 = ldsf(bp + (u32t)(n * 32));
                    float bb1 = ldsf(bp + (u32t)(n * 32) + 4);
                    float v0 = tanh_fast(acc[n][0] + bb0);
                    float v1 = tanh_fast(acc[n][1] + bb1);
                    float v2 = tanh_fast(acc[n][2] + bb0);
                    float v3 = tanh_fast(acc[n][3] + bb1);
                    if (n == 12 && l4 >= 2) { v0 = v1 = v2 = v3 = 0.0f; }  // cols 100..103
                    int kc = n >> 1, f = (n & 1) * 2;
                    split2(v0, v1, aH[kc][f],     aL[kc][f]);
                    split2(v2, v3, aH[kc][f + 1], aL[kc][f + 1]);
                }
            } else {
                // ===== Euler epilogue: x += (acc + b3 - noise)*dt; A <- x, t_next =====
                const float tn = (float)(s + 1) * dt;
                const u32t bp3 = sb + OFF_BIAS + (u32t)(2 * 416 + l4 * 8);
                #pragma unroll
                for (int n = 0; n < NT; n++) {
                    float v0, v1, v2, v3;
                    if (n < 12) {
                        int q0 = n * 8 + l4 * 2, q1 = q0 + 1;   // < 96
                        float bb0 = ldsf(bp3 + (u32t)(n * 32));
                        float bb1 = ldsf(bp3 + (u32t)(n * 32) + 4);
                        float nz0 = gv0 ? __ldg(ps0 + q0 * CNUM) : 0.0f;
                        float nz1 = gv0 ? __ldg(ps0 + q1 * CNUM) : 0.0f;
                        float nz2 = gv1 ? __ldg(ps1 + q0 * CNUM) : 0.0f;
                        float nz3 = gv1 ? __ldg(ps1 + q1 * CNUM) : 0.0f;
                        float x0, x1, x2, x3;
                        lds64(xb0 + (u32t)(n * 32), x0, x1);
                        lds64(xb1 + (u32t)(n * 32), x2, x3);
                        v0 = fmaf((acc[n][0] + bb0) - nz0, dt, x0);
                        v1 = fmaf((acc[n][1] + bb1) - nz1, dt, x1);
                        v2 = fmaf((acc[n][2] + bb0) - nz2, dt, x2);
                        v3 = fmaf((acc[n][3] + bb1) - nz3, dt, x3);
                        sts64(xb0 + (u32t)(n * 32), v0, v1);
                        sts64(xb1 + (u32t)(n * 32), v2, v3);
                    } else {
                        // tile 12: col 96 = x update (noise = rand_error); col 97 = t; else 0
                        if (l4 == 0) {
                            float bb0 = ldsf(bp3 + (u32t)(n * 32));
                            float nz0 = gv0 ? __ldg(pr0) : 0.0f;
                            float nz2 = gv1 ? __ldg(pr1) : 0.0f;
                            float x0, x2;
                            x0 = ldsf(xb0 + (u32t)(n * 32));
                            x2 = ldsf(xb1 + (u32t)(n * 32));
                            v0 = fmaf((acc[n][0] + bb0) - nz0, dt, x0);
                            v2 = fmaf((acc[n][2] + bb0) - nz2, dt, x2);
                            sts64(xb0 + (u32t)(n * 32), v0, tn);
                            sts64(xb1 + (u32t)(n * 32), v2, tn);
                            v1 = tn; v3 = tn;
                        } else {
                            v0 = v1 = v2 = v3 = 0.0f;
                        }
                    }
                    int kc = n >> 1, f = (n & 1) * 2;
                    split2(v0, v1, aH[kc][f],     aL[kc][f]);
                    split2(v2, v3, aH[kc][f + 1], aL[kc][f + 1]);
                }
            }
        }
    }

    // ---- write result (B, 97, C) from x smem (warp-private rows) ----
    #pragma unroll
    for (int n = 0; n < NT; n++) {
        int q0 = n * 8 + l4 * 2, q1 = q0 + 1;
        float x0, x1, x2, x3;
        lds64(xb0 + (u32t)(n * 32), x0, x1);
        lds64(xb1 + (u32t)(n * 32), x2, x3);
        if (gv0 && q0 < QP1) out[((size_t)gb0 * QP1 + q0) * CNUM + gc0] = x0;
        if (gv0 && q1 < QP1) out[((size_t)gb0 * QP1 + q1) * CNUM + gc0] = x1;
        if (gv1 && q0 < QP1) out[((size_t)gb1 * QP1 + q0) * CNUM + gc1] = x2;
        if (gv1 && q1 < QP1) out[((size_t)gb1 * QP1 + q1) * CNUM + gc1] = x3;
    }
}

extern "C" void kernel_launch(void* const* d_in, const int* in_sizes, int n_in,
                              void* d_out, int out_size)
{
    const float* series     = (const float*)d_in[0];
    const float* rand_error = (const float*)d_in[1];
    const float* W1 = (const float*)d_in[2];
    const float* b1 = (const float*)d_in[3];
    const float* W2 = (const float*)d_in[4];
    const float* b2 = (const float*)d_in[5];
    const float* W3 = (const float*)d_in[6];
    const float* b3 = (const float*)d_in[7];
    float* out = (float*)d_out;

    cudaFuncSetAttribute(arima_mma_kernel,
                         cudaFuncAttributeMaxDynamicSharedMemorySize, SMEM_TOTAL);
    arima_mma_kernel<<<GRID, NTHREADS, SMEM_TOTAL>>>(
        series, rand_error, W1, b1, W2, b2, W3, b3, out);
}

// round 15
// speedup vs baseline: 1.4895x; 1.0687x over previous
#include <cuda_runtime.h>
#include <cuda_bf16.h>
#include <cstdint>

typedef unsigned int u32t;

#define BNUM 1024
#define QNUM 96
#define CNUM 16
#define HNUM 100
#define NSTEPS_K 100
#define QP1 97
#define ROWS (BNUM*CNUM)
#define MT 128            // rows per CTA (exact: 16384 = 128 x 128)
#define GRID 128
#define NTHREADS 256      // 8 warps, warp w owns rows w*16..w*16+15 (2/SMSP)
#define NT 13             // n8 tiles per warp (full width)

#define SWB 208           // W row stride bytes (104 bf16) = 52 words, conflict-free
#define ROW8 (8*SWB)      // 1664

// SMEM: W (bf16 hi/lo) + bias + x state (fp32)
#define WBUF  (104*SWB)              // 21632 (W1hi W1lo W2hi W2lo W3hi W3lo)
#define OFF_W 0
#define OFF_BIAS (6*WBUF)            // 129792 ; bias[l][104] fp32
#define OFF_X    (OFF_BIAS + 1280)   // 131072
#define XSTR  106                    // floats per x row (EVEN -> v2.f32 aligned)
#define SMEM_TOTAL (OFF_X + 128*XSTR*4)   // 185344

extern __shared__ char smbase[];

__device__ __forceinline__ u32t smem_u32(const void* p) {
    u32t a;
    asm("{ .reg .u64 t; cvta.to.shared.u64 t, %1; cvt.u32.u64 %0, t; }" : "=r"(a) : "l"(p));
    return a;
}
__device__ __forceinline__ float tanh_fast(float x) {
    asm("tanh.approx.f32 %0, %0;" : "+f"(x));
    return x;
}
__device__ __forceinline__ u32t ldsw(u32t a) {
    u32t v; asm("ld.shared.b32 %0, [%1];" : "=r"(v) : "r"(a)); return v;
}
__device__ __forceinline__ float ldsf(u32t a) {
    float v; asm("ld.shared.f32 %0, [%1];" : "=f"(v) : "r"(a)); return v;
}
__device__ __forceinline__ void lds64(u32t a, float& x, float& y) {
    asm("ld.shared.v2.f32 {%0, %1}, [%2];" : "=f"(x), "=f"(y) : "r"(a));
}
__device__ __forceinline__ void sts64(u32t a, float x, float y) {
    asm volatile("st.shared.v2.f32 [%0], {%1, %2};" :: "r"(a), "f"(x), "f"(y));
}
// pack (v0 -> low bf16, v1 -> high bf16) plus bf16 residual pair
__device__ __forceinline__ void split2(float v0, float v1, u32t& hi, u32t& lo) {
    asm("cvt.rn.bf16x2.f32 %0, %1, %2;" : "=r"(hi) : "f"(v1), "f"(v0));
    float h0 = __uint_as_float(hi << 16);
    float h1 = __uint_as_float(hi & 0xFFFF0000u);
    float l0 = v0 - h0, l1 = v1 - h1;
    asm("cvt.rn.bf16x2.f32 %0, %1, %2;" : "=r"(lo) : "f"(l1), "f"(l0));
}
__device__ __forceinline__ void mma16(float (&d)[4], u32t a0, u32t a1, u32t a2, u32t a3,
                                      u32t b0, u32t b1) {
    asm volatile("mma.sync.aligned.m16n8k16.row.col.f32.bf16.bf16.f32 "
        "{%0,%1,%2,%3}, {%4,%5,%6,%7}, {%8,%9}, {%0,%1,%2,%3};"
        : "+f"(d[0]), "+f"(d[1]), "+f"(d[2]), "+f"(d[3])
        : "r"(a0), "r"(a1), "r"(a2), "r"(a3), "r"(b0), "r"(b1));
}
__device__ __forceinline__ void mma8(float (&d)[4], u32t a0, u32t a1, u32t b0) {
    asm volatile("mma.sync.aligned.m16n8k8.row.col.f32.bf16.bf16.f32 "
        "{%0,%1,%2,%3}, {%4,%5}, {%6}, {%0,%1,%2,%3};"
        : "+f"(d[0]), "+f"(d[1]), "+f"(d[2]), "+f"(d[3])
        : "r"(a0), "r"(a1), "r"(b0));
}

__global__ __launch_bounds__(NTHREADS, 1)
void arima_mma_kernel(const float* __restrict__ series,
                      const float* __restrict__ rand_error,
                      const float* __restrict__ W1, const float* __restrict__ b1,
                      const float* __restrict__ W2, const float* __restrict__ b2,
                      const float* __restrict__ W3, const float* __restrict__ b3,
                      float* __restrict__ out)
{
    const u32t sb = smem_u32(smbase);
    const int tid  = threadIdx.x;
    const int w    = tid >> 5;
    const int lane = tid & 31;
    const int l4   = lane & 3;
    const int lr   = lane >> 2;
    const int base = blockIdx.x * MT;
    const int r0   = w * 16 + lr;    // fragment row (0..127)
    const float dt = 1.0f / (float)NSTEPS_K;

    // ---- zero smem ----
    for (int i = tid; i < SMEM_TOTAL / 4; i += NTHREADS)
        ((u32t*)smbase)[i] = 0u;
    __syncthreads();

    // ---- weights -> SMEM bf16 hi/lo, row-major [j][k], stride 104 ----
    char* Wp = smbase + OFF_W;
    for (int idx = tid; idx < HNUM * (QNUM + 2); idx += NTHREADS) {
        int j = idx / (QNUM + 2), k = idx - j * (QNUM + 2);
        float v = W1[idx];
        __nv_bfloat16 h = __float2bfloat16(v);
        __nv_bfloat16 l = __float2bfloat16(v - __bfloat162float(h));
        u32t o = (u32t)(j * SWB + k * 2);
        *(__nv_bfloat16*)(Wp + 0 * WBUF + o) = h;
        *(__nv_bfloat16*)(Wp + 1 * WBUF + o) = l;
    }
    for (int idx = tid; idx < HNUM * HNUM; idx += NTHREADS) {
        int j = idx / HNUM, k = idx - j * HNUM;
        float v = W2[idx];
        __nv_bfloat16 h = __float2bfloat16(v);
        __nv_bfloat16 l = __float2bfloat16(v - __bfloat162float(h));
        u32t o = (u32t)(j * SWB + k * 2);
        *(__nv_bfloat16*)(Wp + 2 * WBUF + o) = h;
        *(__nv_bfloat16*)(Wp + 3 * WBUF + o) = l;
    }
    for (int idx = tid; idx < QP1 * HNUM; idx += NTHREADS) {
        int j = idx / HNUM, k = idx - j * HNUM;
        float v = W3[idx];
        __nv_bfloat16 h = __float2bfloat16(v);
        __nv_bfloat16 l = __float2bfloat16(v - __bfloat162float(h));
        u32t o = (u32t)(j * SWB + k * 2);
        *(__nv_bfloat16*)(Wp + 4 * WBUF + o) = h;
        *(__nv_bfloat16*)(Wp + 5 * WBUF + o) = l;
    }
    float* biasp = (float*)(smbase + OFF_BIAS);
    for (int j = tid; j < HNUM; j += NTHREADS) {
        biasp[j]       = b1[j];
        biasp[104 + j] = b2[j];
    }
    for (int j = tid; j < QP1; j += NTHREADS) biasp[208 + j] = b3[j];

    // ---- per-thread global row helpers (all rows valid: 16384 = 128*128) ----
    const int grow0 = base + r0, grow1 = grow0 + 8;
    const int gb0 = grow0 >> 4, gc0 = grow0 & 15;
    const int gb1 = grow1 >> 4, gc1 = grow1 & 15;
    const float* ps0 = series + (size_t)gb0 * (QNUM * CNUM) + gc0;
    const float* ps1 = series + (size_t)gb1 * (QNUM * CNUM) + gc1;
    const float* pr0 = rand_error + (size_t)gb0 * CNUM + gc0;
    const float* pr1 = rand_error + (size_t)gb1 * CNUM + gc1;

    // x smem addresses for this thread's fragment positions (8B aligned: XSTR even)
    const u32t xb0 = sb + OFF_X + (u32t)(r0 * XSTR + l4 * 2) * 4;        // row r0
    const u32t xb1 = sb + OFF_X + (u32t)((r0 + 8) * XSTR + l4 * 2) * 4;  // row r0+8

    // ---- A fragments live in registers: aH/aL[kc][frag] (kc=6 uses [0..1]) ----
    u32t aH[7][4], aL[7][4];

    // ---- init: load x0, store to x smem, build initial A fragments (t=0) ----
    #pragma unroll
    for (int n = 0; n < NT; n++) {
        int q0 = n * 8 + l4 * 2, q1 = q0 + 1;
        float v0 = (q0 < QNUM) ? __ldg(ps0 + q0 * CNUM) : (q0 == QNUM) ? __ldg(pr0) : 0.0f;
        float v1 = (q1 < QNUM) ? __ldg(ps0 + q1 * CNUM) : 0.0f;
        float v2 = (q0 < QNUM) ? __ldg(ps1 + q0 * CNUM) : (q0 == QNUM) ? __ldg(pr1) : 0.0f;
        float v3 = (q1 < QNUM) ? __ldg(ps1 + q1 * CNUM) : 0.0f;
        sts64(xb0 + (u32t)(n * 32), v0, v1);   // x state (col 97 slot unused)
        sts64(xb1 + (u32t)(n * 32), v2, v3);
        // A fragment: col 97 = t (=0 at step 0); cols>=98 zero (already)
        int kc = n >> 1, f = (n & 1) * 2;
        split2(v0, v1, aH[kc][f],     aL[kc][f]);
        split2(v2, v3, aH[kc][f + 1], aL[kc][f + 1]);
    }
    __syncthreads();  // weights visible (x/A are warp-private)

    const u32t wJ = (u32t)(lr * SWB + l4 * 4);

    for (int s = 0; s < NSTEPS_K; s++) {
        #pragma unroll 1
        for (int l = 0; l < 3; l++) {
            float acc[NT][4];
            #pragma unroll
            for (int n = 0; n < NT; n++)
                #pragma unroll
                for (int e = 0; e < 4; e++) acc[n][e] = 0.0f;

            const u32t wHb = sb + OFF_W + (u32t)l * (2 * WBUF) + wJ;
            const u32t wLb = wHb + WBUF;

            #pragma unroll
            for (int kc = 0; kc < 6; kc++) {
                u32t ko = (u32t)(kc * 32);
                #pragma unroll
                for (int n = 0; n < NT; n++) {
                    u32t wo = ko + (u32t)(n * ROW8);
                    u32t bh0 = ldsw(wHb + wo), bh1 = ldsw(wHb + wo + 16);
                    u32t bl0 = ldsw(wLb + wo), bl1 = ldsw(wLb + wo + 16);
                    mma16(acc[n], aH[kc][0], aH[kc][1], aH[kc][2], aH[kc][3], bh0, bh1);
                    mma16(acc[n], aH[kc][0], aH[kc][1], aH[kc][2], aH[kc][3], bl0, bl1);
                    mma16(acc[n], aL[kc][0], aL[kc][1], aL[kc][2], aL[kc][3], bh0, bh1);
                }
            }
            {   // k8 tail: k = 96..103
                u32t ko = 192;
                #pragma unroll
                for (int n = 0; n < NT; n++) {
                    u32t wo = ko + (u32t)(n * ROW8);
                    u32t bh0 = ldsw(wHb + wo);
                    u32t bl0 = ldsw(wLb + wo);
                    mma8(acc[n], aH[6][0], aH[6][1], bh0);
                    mma8(acc[n], aH[6][0], aH[6][1], bl0);
                    mma8(acc[n], aL[6][0], aL[6][1], bh0);
                }
            }

            if (l < 2) {
                // ===== hidden epilogue: A <- tanh(acc + bias), in registers =====
                const u32t bp = sb + OFF_BIAS + (u32t)(l * 416 + l4 * 8);
                #pragma unroll
                for (int n = 0; n < NT; n++) {
                    float bb0 = ldsf(bp + (u32t)(n * 32));
                    float bb1 = ldsf(bp + (u32t)(n * 32) + 4);
                    float v0 = tanh_fast(acc[n][0] + bb0);
                    float v1 = tanh_fast(acc[n][1] + bb1);
                    float v2 = tanh_fast(acc[n][2] + bb0);
                    float v3 = tanh_fast(acc[n][3] + bb1);
                    if (n == 12 && l4 >= 2) { v0 = v1 = v2 = v3 = 0.0f; }  // cols 100..103
                    int kc = n >> 1, f = (n & 1) * 2;
                    split2(v0, v1, aH[kc][f],     aL[kc][f]);
                    split2(v2, v3, aH[kc][f + 1], aL[kc][f + 1]);
                }
            } else {
                // ===== Euler epilogue: x += (acc + b3 - noise)*dt; A <- x, t_next =====
                const float tn = (float)(s + 1) * dt;
                const u32t bp3 = sb + OFF_BIAS + (u32t)(2 * 416 + l4 * 8);
                #pragma unroll
                for (int n = 0; n < NT; n++) {
                    float v0, v1, v2, v3;
                    if (n < 12) {
                        int q0 = n * 8 + l4 * 2, q1 = q0 + 1;   // < 96
                        float bb0 = ldsf(bp3 + (u32t)(n * 32));
                        float bb1 = ldsf(bp3 + (u32t)(n * 32) + 4);
                        float nz0 = __ldg(ps0 + q0 * CNUM);
                        float nz1 = __ldg(ps0 + q1 * CNUM);
                        float nz2 = __ldg(ps1 + q0 * CNUM);
                        float nz3 = __ldg(ps1 + q1 * CNUM);
                        float x0, x1, x2, x3;
                        lds64(xb0 + (u32t)(n * 32), x0, x1);
                        lds64(xb1 + (u32t)(n * 32), x2, x3);
                        v0 = fmaf((acc[n][0] + bb0) - nz0, dt, x0);
                        v1 = fmaf((acc[n][1] + bb1) - nz1, dt, x1);
                        v2 = fmaf((acc[n][2] + bb0) - nz2, dt, x2);
                        v3 = fmaf((acc[n][3] + bb1) - nz3, dt, x3);
                        sts64(xb0 + (u32t)(n * 32), v0, v1);
                        sts64(xb1 + (u32t)(n * 32), v2, v3);
                    } else {
                        // tile 12: col 96 = x update (noise = rand_error); col 97 = t; else 0
                        if (l4 == 0) {
                            float bb0 = ldsf(bp3 + (u32t)(n * 32));
                            float nz0 = __ldg(pr0);
                            float nz2 = __ldg(pr1);
                            float x0, x2;
                            x0 = ldsf(xb0 + (u32t)(n * 32));
                            x2 = ldsf(xb1 + (u32t)(n * 32));
                            v0 = fmaf((acc[n][0] + bb0) - nz0, dt, x0);
                            v2 = fmaf((acc[n][2] + bb0) - nz2, dt, x2);
                            sts64(xb0 + (u32t)(n * 32), v0, tn);
                            sts64(xb1 + (u32t)(n * 32), v2, tn);
                            v1 = tn; v3 = tn;
                        } else {
                            v0 = v1 = v2 = v3 = 0.0f;
                        }
                    }
                    int kc = n >> 1, f = (n & 1) * 2;
                    split2(v0, v1, aH[kc][f],     aL[kc][f]);
                    split2(v2, v3, aH[kc][f + 1], aL[kc][f + 1]);
                }
            }
        }
    }

    // ---- write result (B, 97, C) from x smem (warp-private rows) ----
    #pragma unroll
    for (int n = 0; n < NT; n++) {
        int q0 = n * 8 + l4 * 2, q1 = q0 + 1;
        float x0, x1, x2, x3;
        lds64(xb0 + (u32t)(n * 32), x0, x1);
        lds64(xb1 + (u32t)(n * 32), x2, x3);
        if (q0 < QP1) out[((size_t)gb0 * QP1 + q0) * CNUM + gc0] = x0;
        if (q1 < QP1) out[((size_t)gb0 * QP1 + q1) * CNUM + gc0] = x1;
        if (q0 < QP1) out[((size_t)gb1 * QP1 + q0) * CNUM + gc1] = x2;
        if (q1 < QP1) out[((size_t)gb1 * QP1 + q1) * CNUM + gc1] = x3;
    }
}

extern "C" void kernel_launch(void* const* d_in, const int* in_sizes, int n_in,
                              void* d_out, int out_size)
{
    const float* series     = (const float*)d_in[0];
    const float* rand_error = (const float*)d_in[1];
    const float* W1 = (const float*)d_in[2];
    const float* b1 = (const float*)d_in[3];
    const float* W2 = (const float*)d_in[4];
    const float* b2 = (const float*)d_in[5];
    const float* W3 = (const float*)d_in[6];
    const float* b3 = (const float*)d_in[7];
    float* out = (float*)d_out;

    cudaFuncSetAttribute(arima_mma_kernel,
                         cudaFuncAttributeMaxDynamicSharedMemorySize, SMEM_TOTAL);
    arima_mma_kernel<<<GRID, NTHREADS, SMEM_TOTAL>>>(
        series, rand_error, W1, b1, W2, b2, W3, b3, out);
}

// round 16
// speedup vs baseline: 1.5391x; 1.0333x over previous
#include <cuda_runtime.h>
#include <cuda_bf16.h>
#include <cstdint>

typedef unsigned int u32t;

#define BNUM 1024
#define QNUM 96
#define CNUM 16
#define HNUM 100
#define NSTEPS_K 100
#define QP1 97
#define ROWS (BNUM*CNUM)
#define MT 128
#define GRID 128
#define NTHREADS 256      // 8 warps, warp w owns rows w*16..w*16+15
#define NT 13

// Packed weight layout: chunk(l, kc, n) = 512 B, lane i holds 16 B:
//   [bh0, bh1, bl0, bl1] for (j = n*8 + (i>>2), k0 = kc*16 + (i&3)*2)
//   kc==6 (k8 tail): [bh0, bl0, 0, 0]
#define CHUNK 512
#define LCH   (7*13*CHUNK)           // 46592 per layer
#define OFF_W 0
#define OFF_BIAS (3*LCH)             // 139776 ; bias[l][104] fp32
#define OFF_X    (OFF_BIAS + 1280)   // 141056
#define XSTR  106                    // floats per x row (even -> 8B aligned v2)
#define SMEM_TOTAL (OFF_X + 128*XSTR*4)   // 195328

extern __shared__ char smbase[];

__device__ __forceinline__ u32t smem_u32(const void* p) {
    u32t a;
    asm("{ .reg .u64 t; cvta.to.shared.u64 t, %1; cvt.u32.u64 %0, t; }" : "=r"(a) : "l"(p));
    return a;
}
__device__ __forceinline__ float tanh_fast(float x) {
    asm("tanh.approx.f32 %0, %0;" : "+f"(x));
    return x;
}
__device__ __forceinline__ float ldsf(u32t a) {
    float v; asm("ld.shared.f32 %0, [%1];" : "=f"(v) : "r"(a)); return v;
}
__device__ __forceinline__ void lds64(u32t a, float& x, float& y) {
    asm("ld.shared.v2.f32 {%0, %1}, [%2];" : "=f"(x), "=f"(y) : "r"(a));
}
__device__ __forceinline__ void sts64(u32t a, float x, float y) {
    asm volatile("st.shared.v2.f32 [%0], {%1, %2};" :: "r"(a), "f"(x), "f"(y));
}
__device__ __forceinline__ void lds128u(u32t a, u32t& x0, u32t& x1, u32t& x2, u32t& x3) {
    asm("ld.shared.v4.b32 {%0, %1, %2, %3}, [%4];"
        : "=r"(x0), "=r"(x1), "=r"(x2), "=r"(x3) : "r"(a));
}
__device__ __forceinline__ void lds64u(u32t a, u32t& x0, u32t& x1) {
    asm("ld.shared.v2.b32 {%0, %1}, [%2];" : "=r"(x0), "=r"(x1) : "r"(a));
}
// pack (v0 -> low bf16, v1 -> high bf16) plus bf16 residual pair
__device__ __forceinline__ void split2(float v0, float v1, u32t& hi, u32t& lo) {
    asm("cvt.rn.bf16x2.f32 %0, %1, %2;" : "=r"(hi) : "f"(v1), "f"(v0));
    float h0 = __uint_as_float(hi << 16);
    float h1 = __uint_as_float(hi & 0xFFFF0000u);
    float l0 = v0 - h0, l1 = v1 - h1;
    asm("cvt.rn.bf16x2.f32 %0, %1, %2;" : "=r"(lo) : "f"(l1), "f"(l0));
}
__device__ __forceinline__ void mma16(float (&d)[4], u32t a0, u32t a1, u32t a2, u32t a3,
                                      u32t b0, u32t b1) {
    asm volatile("mma.sync.aligned.m16n8k16.row.col.f32.bf16.bf16.f32 "
        "{%0,%1,%2,%3}, {%4,%5,%6,%7}, {%8,%9}, {%0,%1,%2,%3};"
        : "+f"(d[0]), "+f"(d[1]), "+f"(d[2]), "+f"(d[3])
        : "r"(a0), "r"(a1), "r"(a2), "r"(a3), "r"(b0), "r"(b1));
}
__device__ __forceinline__ void mma8(float (&d)[4], u32t a0, u32t a1, u32t b0) {
    asm volatile("mma.sync.aligned.m16n8k8.row.col.f32.bf16.bf16.f32 "
        "{%0,%1,%2,%3}, {%4,%5}, {%6}, {%0,%1,%2,%3};"
        : "+f"(d[0]), "+f"(d[1]), "+f"(d[2]), "+f"(d[3])
        : "r"(a0), "r"(a1), "r"(b0));
}

__global__ __launch_bounds__(NTHREADS, 1)
void arima_mma_kernel(const float* __restrict__ series,
                      const float* __restrict__ rand_error,
                      const float* __restrict__ W1, const float* __restrict__ b1,
                      const float* __restrict__ W2, const float* __restrict__ b2,
                      const float* __restrict__ W3, const float* __restrict__ b3,
                      float* __restrict__ out)
{
    const u32t sb = smem_u32(smbase);
    const int tid  = threadIdx.x;
    const int w    = tid >> 5;
    const int lane = tid & 31;
    const int l4   = lane & 3;
    const int lr   = lane >> 2;
    const int base = blockIdx.x * MT;
    const int r0   = w * 16 + lr;
    const float dt = 1.0f / (float)NSTEPS_K;

    // ---- zero smem ----
    for (int i = tid; i < SMEM_TOTAL / 4; i += NTHREADS)
        ((u32t*)smbase)[i] = 0u;
    __syncthreads();

    // ---- weights -> packed lane-order fragment chunks ----
    // getW(l, j, k): logical weight for layer l, output j, input k
    auto getW = [&](int l, int j, int k) -> float {
        if (l == 0) return (j < HNUM && k < QNUM + 2) ? W1[j * (QNUM + 2) + k] : 0.0f;
        if (l == 1) return (j < HNUM && k < HNUM) ? W2[j * HNUM + k] : 0.0f;
        return (j < QP1 && k < HNUM) ? W3[j * HNUM + k] : 0.0f;
    };
    for (int idx = tid; idx < 3 * 7 * 13 * 32; idx += NTHREADS) {
        int lane_c = idx & 31;
        int rest = idx >> 5;
        int n = rest % 13; rest /= 13;
        int kc = rest % 7;
        int l = rest / 7;
        int j  = n * 8 + (lane_c >> 2);
        int k0 = kc * 16 + (lane_c & 3) * 2;
        float va0 = getW(l, j, k0),     va1 = getW(l, j, k0 + 1);
        float vb0 = getW(l, j, k0 + 8), vb1 = getW(l, j, k0 + 9);
        u32t h0, l0, h1, l1;
        split2(va0, va1, h0, l0);
        split2(vb0, vb1, h1, l1);
        u32t* chunk = (u32t*)(smbase + OFF_W + (size_t)((l * 7 + kc) * 13 + n) * CHUNK
                              + lane_c * 16);
        if (kc < 6) { chunk[0] = h0; chunk[1] = h1; chunk[2] = l0; chunk[3] = l1; }
        else        { chunk[0] = h0; chunk[1] = l0; chunk[2] = 0;  chunk[3] = 0;  }
    }
    float* biasp = (float*)(smbase + OFF_BIAS);
    for (int j = tid; j < HNUM; j += NTHREADS) {
        biasp[j]       = b1[j];
        biasp[104 + j] = b2[j];
    }
    for (int j = tid; j < QP1; j += NTHREADS) biasp[208 + j] = b3[j];

    // ---- per-thread global row helpers (all rows valid) ----
    const int grow0 = base + r0, grow1 = grow0 + 8;
    const int gb0 = grow0 >> 4, gc0 = grow0 & 15;
    const int gb1 = grow1 >> 4, gc1 = grow1 & 15;
    const float* ps0 = series + (size_t)gb0 * (QNUM * CNUM) + gc0;
    const float* ps1 = series + (size_t)gb1 * (QNUM * CNUM) + gc1;
    const float* pr0 = rand_error + (size_t)gb0 * CNUM + gc0;
    const float* pr1 = rand_error + (size_t)gb1 * CNUM + gc1;

    const u32t xb0 = sb + OFF_X + (u32t)(r0 * XSTR + l4 * 2) * 4;
    const u32t xb1 = sb + OFF_X + (u32t)((r0 + 8) * XSTR + l4 * 2) * 4;

    // ---- A fragments in registers ----
    u32t aH[7][4], aL[7][4];

    #pragma unroll
    for (int n = 0; n < NT; n++) {
        int q0 = n * 8 + l4 * 2, q1 = q0 + 1;
        float v0 = (q0 < QNUM) ? __ldg(ps0 + q0 * CNUM) : (q0 == QNUM) ? __ldg(pr0) : 0.0f;
        float v1 = (q1 < QNUM) ? __ldg(ps0 + q1 * CNUM) : 0.0f;
        float v2 = (q0 < QNUM) ? __ldg(ps1 + q0 * CNUM) : (q0 == QNUM) ? __ldg(pr1) : 0.0f;
        float v3 = (q1 < QNUM) ? __ldg(ps1 + q1 * CNUM) : 0.0f;
        sts64(xb0 + (u32t)(n * 32), v0, v1);
        sts64(xb1 + (u32t)(n * 32), v2, v3);
        int kc = n >> 1, f = (n & 1) * 2;
        split2(v0, v1, aH[kc][f],     aL[kc][f]);
        split2(v2, v3, aH[kc][f + 1], aL[kc][f + 1]);
    }
    __syncthreads();  // weights visible

    const u32t wLane = sb + OFF_W + (u32t)(lane * 16);

    for (int s = 0; s < NSTEPS_K; s++) {
        #pragma unroll 1
        for (int l = 0; l < 3; l++) {
            float acc[NT][4];
            #pragma unroll
            for (int n = 0; n < NT; n++)
                #pragma unroll
                for (int e = 0; e < 4; e++) acc[n][e] = 0.0f;

            const u32t wb = wLane + (u32t)(l * LCH);

            #pragma unroll
            for (int kc = 0; kc < 6; kc++) {
                // stage: burst-load all 13 fragment chunks for this kc
                u32t wr[NT][4];
                #pragma unroll
                for (int n = 0; n < NT; n++)
                    lds128u(wb + (u32t)((kc * 13 + n) * CHUNK),
                            wr[n][0], wr[n][1], wr[n][2], wr[n][3]);
                // fire: 39 MMAs
                #pragma unroll
                for (int n = 0; n < NT; n++) {
                    mma16(acc[n], aH[kc][0], aH[kc][1], aH[kc][2], aH[kc][3], wr[n][0], wr[n][1]);
                    mma16(acc[n], aH[kc][0], aH[kc][1], aH[kc][2], aH[kc][3], wr[n][2], wr[n][3]);
                    mma16(acc[n], aL[kc][0], aL[kc][1], aL[kc][2], aL[kc][3], wr[n][0], wr[n][1]);
                }
            }
            {   // k8 tail
                u32t wt[NT][2];
                #pragma unroll
                for (int n = 0; n < NT; n++)
                    lds64u(wb + (u32t)((6 * 13 + n) * CHUNK), wt[n][0], wt[n][1]);
                #pragma unroll
                for (int n = 0; n < NT; n++) {
                    mma8(acc[n], aH[6][0], aH[6][1], wt[n][0]);
                    mma8(acc[n], aH[6][0], aH[6][1], wt[n][1]);
                    mma8(acc[n], aL[6][0], aL[6][1], wt[n][0]);
                }
            }

            if (l < 2) {
                // ===== hidden epilogue: A <- tanh(acc + bias), in registers =====
                const u32t bp = sb + OFF_BIAS + (u32t)(l * 416 + l4 * 8);
                #pragma unroll
                for (int n = 0; n < NT; n++) {
                    float bb0 = ldsf(bp + (u32t)(n * 32));
                    float bb1 = ldsf(bp + (u32t)(n * 32) + 4);
                    float v0 = tanh_fast(acc[n][0] + bb0);
                    float v1 = tanh_fast(acc[n][1] + bb1);
                    float v2 = tanh_fast(acc[n][2] + bb0);
                    float v3 = tanh_fast(acc[n][3] + bb1);
                    if (n == 12 && l4 >= 2) { v0 = v1 = v2 = v3 = 0.0f; }
                    int kc = n >> 1, f = (n & 1) * 2;
                    split2(v0, v1, aH[kc][f],     aL[kc][f]);
                    split2(v2, v3, aH[kc][f + 1], aL[kc][f + 1]);
                }
            } else {
                // ===== Euler epilogue =====
                const float tn = (float)(s + 1) * dt;
                const u32t bp3 = sb + OFF_BIAS + (u32t)(2 * 416 + l4 * 8);
                #pragma unroll
                for (int n = 0; n < NT; n++) {
                    float v0, v1, v2, v3;
                    if (n < 12) {
                        int q0 = n * 8 + l4 * 2, q1 = q0 + 1;
                        float bb0 = ldsf(bp3 + (u32t)(n * 32));
                        float bb1 = ldsf(bp3 + (u32t)(n * 32) + 4);
                        float nz0 = __ldg(ps0 + q0 * CNUM);
                        float nz1 = __ldg(ps0 + q1 * CNUM);
                        float nz2 = __ldg(ps1 + q0 * CNUM);
                        float nz3 = __ldg(ps1 + q1 * CNUM);
                        float x0, x1, x2, x3;
                        lds64(xb0 + (u32t)(n * 32), x0, x1);
                        lds64(xb1 + (u32t)(n * 32), x2, x3);
                        v0 = fmaf((acc[n][0] + bb0) - nz0, dt, x0);
                        v1 = fmaf((acc[n][1] + bb1) - nz1, dt, x1);
                        v2 = fmaf((acc[n][2] + bb0) - nz2, dt, x2);
                        v3 = fmaf((acc[n][3] + bb1) - nz3, dt, x3);
                        sts64(xb0 + (u32t)(n * 32), v0, v1);
                        sts64(xb1 + (u32t)(n * 32), v2, v3);
                    } else {
                        if (l4 == 0) {
                            float bb0 = ldsf(bp3 + (u32t)(n * 32));
                            float nz0 = __ldg(pr0);
                            float nz2 = __ldg(pr1);
                            float x0 = ldsf(xb0 + (u32t)(n * 32));
                            float x2 = ldsf(xb1 + (u32t)(n * 32));
                            v0 = fmaf((acc[n][0] + bb0) - nz0, dt, x0);
                            v2 = fmaf((acc[n][2] + bb0) - nz2, dt, x2);
                            sts64(xb0 + (u32t)(n * 32), v0, tn);
                            sts64(xb1 + (u32t)(n * 32), v2, tn);
                            v1 = tn; v3 = tn;
                        } else {
                            v0 = v1 = v2 = v3 = 0.0f;
                        }
                    }
                    int kc = n >> 1, f = (n & 1) * 2;
                    split2(v0, v1, aH[kc][f],     aL[kc][f]);
                    split2(v2, v3, aH[kc][f + 1], aL[kc][f + 1]);
                }
            }
        }
    }

    // ---- write result (B, 97, C) ----
    #pragma unroll
    for (int n = 0; n < NT; n++) {
        int q0 = n * 8 + l4 * 2, q1 = q0 + 1;
        float x0, x1, x2, x3;
        lds64(xb0 + (u32t)(n * 32), x0, x1);
        lds64(xb1 + (u32t)(n * 32), x2, x3);
        if (q0 < QP1) out[((size_t)gb0 * QP1 + q0) * CNUM + gc0] = x0;
        if (q1 < QP1) out[((size_t)gb0 * QP1 + q1) * CNUM + gc0] = x1;
        if (q0 < QP1) out[((size_t)gb1 * QP1 + q0) * CNUM + gc1] = x2;
        if (q1 < QP1) out[((size_t)gb1 * QP1 + q1) * CNUM + gc1] = x3;
    }
}

extern "C" void kernel_launch(void* const* d_in, const int* in_sizes, int n_in,
                              void* d_out, int out_size)
{
    const float* series     = (const float*)d_in[0];
    const float* rand_error = (const float*)d_in[1];
    const float* W1 = (const float*)d_in[2];
    const float* b1 = (const float*)d_in[3];
    const float* W2 = (const float*)d_in[4];
    const float* b2 = (const float*)d_in[5];
    const float* W3 = (const float*)d_in[6];
    const float* b3 = (const float*)d_in[7];
    float* out = (float*)d_out;

    cudaFuncSetAttribute(arima_mma_kernel,
                         cudaFuncAttributeMaxDynamicSharedMemorySize, SMEM_TOTAL);
    arima_mma_kernel<<<GRID, NTHREADS, SMEM_TOTAL>>>(
        series, rand_error, W1, b1, W2, b2, W3, b3, out);
}

// round 17
// speedup vs baseline: 1.8485x; 1.2011x over previous
#include <cuda_runtime.h>
#include <cuda_fp16.h>
#include <cstdint>

typedef unsigned int u32t;

#define BNUM 1024
#define QNUM 96
#define CNUM 16
#define HNUM 100
#define NSTEPS_K 100
#define QP1 97
#define ROWS (BNUM*CNUM)
#define MT 128
#define GRID 128
#define NTHREADS 256      // 8 warps, warp w owns rows w*16..w*16+15
#define NT 13

// Packed weight layout: chunk(l, kc, n) = 512 B, lane i holds 16 B:
//   [wh0, wh1, wl0, wl1] (fp16x2 words) for (j = n*8 + (i>>2), k0 = kc*16 + (i&3)*2)
//   kc==6 (k8 tail): [wh0, wl0, 0, 0]
#define CHUNK 512
#define LCH   (7*13*CHUNK)           // 46592 per layer
#define OFF_W 0
#define OFF_BIAS (3*LCH)             // 139776 ; bias[l][104] fp32
#define OFF_X    (OFF_BIAS + 1280)   // 141056
#define XSTR  106                    // floats per x row (even -> 8B aligned v2)
#define SMEM_TOTAL (OFF_X + 128*XSTR*4)   // 195328

extern __shared__ char smbase[];

__device__ __forceinline__ u32t smem_u32(const void* p) {
    u32t a;
    asm("{ .reg .u64 t; cvta.to.shared.u64 t, %1; cvt.u32.u64 %0, t; }" : "=r"(a) : "l"(p));
    return a;
}
__device__ __forceinline__ float tanh_fast(float x) {
    asm("tanh.approx.f32 %0, %0;" : "+f"(x));
    return x;
}
__device__ __forceinline__ float ldsf(u32t a) {
    float v; asm("ld.shared.f32 %0, [%1];" : "=f"(v) : "r"(a)); return v;
}
__device__ __forceinline__ void lds64(u32t a, float& x, float& y) {
    asm("ld.shared.v2.f32 {%0, %1}, [%2];" : "=f"(x), "=f"(y) : "r"(a));
}
__device__ __forceinline__ void sts64(u32t a, float x, float y) {
    asm volatile("st.shared.v2.f32 [%0], {%1, %2};" :: "r"(a), "f"(x), "f"(y));
}
__device__ __forceinline__ void lds128u(u32t a, u32t& x0, u32t& x1, u32t& x2, u32t& x3) {
    asm("ld.shared.v4.b32 {%0, %1, %2, %3}, [%4];"
        : "=r"(x0), "=r"(x1), "=r"(x2), "=r"(x3) : "r"(a));
}
__device__ __forceinline__ void lds64u(u32t a, u32t& x0, u32t& x1) {
    asm("ld.shared.v2.b32 {%0, %1}, [%2];" : "=r"(x0), "=r"(x1) : "r"(a));
}
// pack (v0 -> low fp16, v1 -> high fp16)
__device__ __forceinline__ u32t f16pack(float v0, float v1) {
    u32t r;
    asm("cvt.rn.f16x2.f32 %0, %1, %2;" : "=r"(r) : "f"(v1), "f"(v0));
    return r;
}
__device__ __forceinline__ void mma16(float (&d)[4], u32t a0, u32t a1, u32t a2, u32t a3,
                                      u32t b0, u32t b1) {
    asm volatile("mma.sync.aligned.m16n8k16.row.col.f32.f16.f16.f32 "
        "{%0,%1,%2,%3}, {%4,%5,%6,%7}, {%8,%9}, {%0,%1,%2,%3};"
        : "+f"(d[0]), "+f"(d[1]), "+f"(d[2]), "+f"(d[3])
        : "r"(a0), "r"(a1), "r"(a2), "r"(a3), "r"(b0), "r"(b1));
}
__device__ __forceinline__ void mma8(float (&d)[4], u32t a0, u32t a1, u32t b0) {
    asm volatile("mma.sync.aligned.m16n8k8.row.col.f32.f16.f16.f32 "
        "{%0,%1,%2,%3}, {%4,%5}, {%6}, {%0,%1,%2,%3};"
        : "+f"(d[0]), "+f"(d[1]), "+f"(d[2]), "+f"(d[3])
        : "r"(a0), "r"(a1), "r"(b0));
}

__global__ __launch_bounds__(NTHREADS, 1)
void arima_mma_kernel(const float* __restrict__ series,
                      const float* __restrict__ rand_error,
                      const float* __restrict__ W1, const float* __restrict__ b1,
                      const float* __restrict__ W2, const float* __restrict__ b2,
                      const float* __restrict__ W3, const float* __restrict__ b3,
                      float* __restrict__ out)
{
    const u32t sb = smem_u32(smbase);
    const int tid  = threadIdx.x;
    const int w    = tid >> 5;
    const int lane = tid & 31;
    const int l4   = lane & 3;
    const int lr   = lane >> 2;
    const int base = blockIdx.x * MT;
    const int r0   = w * 16 + lr;
    const float dt = 1.0f / (float)NSTEPS_K;

    // ---- zero smem ----
    for (int i = tid; i < SMEM_TOTAL / 4; i += NTHREADS)
        ((u32t*)smbase)[i] = 0u;
    __syncthreads();

    // ---- weights -> packed lane-order fp16 hi/lo fragment chunks ----
    auto getW = [&](int l, int j, int k) -> float {
        if (l == 0) return (j < HNUM && k < QNUM + 2) ? W1[j * (QNUM + 2) + k] : 0.0f;
        if (l == 1) return (j < HNUM && k < HNUM) ? W2[j * HNUM + k] : 0.0f;
        return (j < QP1 && k < HNUM) ? W3[j * HNUM + k] : 0.0f;
    };
    auto splitW = [&](float v, float& hi, float& lo) {
        __half h = __float2half(v);
        hi = __half2float(h);
        lo = v - hi;
    };
    for (int idx = tid; idx < 3 * 7 * 13 * 32; idx += NTHREADS) {
        int lane_c = idx & 31;
        int rest = idx >> 5;
        int n = rest % 13; rest /= 13;
        int kc = rest % 7;
        int l = rest / 7;
        int j  = n * 8 + (lane_c >> 2);
        int k0 = kc * 16 + (lane_c & 3) * 2;
        float a0h, a0l, a1h, a1l, b0h, b0l, b1h, b1l;
        splitW(getW(l, j, k0),     a0h, a0l);
        splitW(getW(l, j, k0 + 1), a1h, a1l);
        splitW(getW(l, j, k0 + 8), b0h, b0l);
        splitW(getW(l, j, k0 + 9), b1h, b1l);
        u32t h0 = f16pack(a0h, a1h), l0 = f16pack(a0l, a1l);
        u32t h1 = f16pack(b0h, b1h), l1 = f16pack(b0l, b1l);
        u32t* chunk = (u32t*)(smbase + OFF_W + (size_t)((l * 7 + kc) * 13 + n) * CHUNK
                              + lane_c * 16);
        if (kc < 6) { chunk[0] = h0; chunk[1] = h1; chunk[2] = l0; chunk[3] = l1; }
        else        { chunk[0] = h0; chunk[1] = l0; chunk[2] = 0;  chunk[3] = 0;  }
    }
    float* biasp = (float*)(smbase + OFF_BIAS);
    for (int j = tid; j < HNUM; j += NTHREADS) {
        biasp[j]       = b1[j];
        biasp[104 + j] = b2[j];
    }
    for (int j = tid; j < QP1; j += NTHREADS) biasp[208 + j] = b3[j];

    // ---- per-thread global row helpers (all rows valid) ----
    const int grow0 = base + r0, grow1 = grow0 + 8;
    const int gb0 = grow0 >> 4, gc0 = grow0 & 15;
    const int gb1 = grow1 >> 4, gc1 = grow1 & 15;
    const float* ps0 = series + (size_t)gb0 * (QNUM * CNUM) + gc0;
    const float* ps1 = series + (size_t)gb1 * (QNUM * CNUM) + gc1;
    const float* pr0 = rand_error + (size_t)gb0 * CNUM + gc0;
    const float* pr1 = rand_error + (size_t)gb1 * CNUM + gc1;

    const u32t xb0 = sb + OFF_X + (u32t)(r0 * XSTR + l4 * 2) * 4;
    const u32t xb1 = sb + OFF_X + (u32t)((r0 + 8) * XSTR + l4 * 2) * 4;

    // ---- A fragments in registers (fp16, single term) ----
    u32t aF[7][4];

    #pragma unroll
    for (int n = 0; n < NT; n++) {
        int q0 = n * 8 + l4 * 2, q1 = q0 + 1;
        float v0 = (q0 < QNUM) ? __ldg(ps0 + q0 * CNUM) : (q0 == QNUM) ? __ldg(pr0) : 0.0f;
        float v1 = (q1 < QNUM) ? __ldg(ps0 + q1 * CNUM) : 0.0f;
        float v2 = (q0 < QNUM) ? __ldg(ps1 + q0 * CNUM) : (q0 == QNUM) ? __ldg(pr1) : 0.0f;
        float v3 = (q1 < QNUM) ? __ldg(ps1 + q1 * CNUM) : 0.0f;
        sts64(xb0 + (u32t)(n * 32), v0, v1);
        sts64(xb1 + (u32t)(n * 32), v2, v3);
        int kc = n >> 1, f = (n & 1) * 2;
        aF[kc][f]     = f16pack(v0, v1);
        aF[kc][f + 1] = f16pack(v2, v3);
    }
    __syncthreads();  // weights visible

    const u32t wLane = sb + OFF_W + (u32t)(lane * 16);

    for (int s = 0; s < NSTEPS_K; s++) {
        #pragma unroll 1
        for (int l = 0; l < 3; l++) {
            float acc[NT][4];
            #pragma unroll
            for (int n = 0; n < NT; n++)
                #pragma unroll
                for (int e = 0; e < 4; e++) acc[n][e] = 0.0f;

            const u32t wb = wLane + (u32t)(l * LCH);

            #pragma unroll
            for (int kc = 0; kc < 6; kc++) {
                // stage: burst-load all 13 fragment chunks for this kc
                u32t wr[NT][4];
                #pragma unroll
                for (int n = 0; n < NT; n++)
                    lds128u(wb + (u32t)((kc * 13 + n) * CHUNK),
                            wr[n][0], wr[n][1], wr[n][2], wr[n][3]);
                // fire: 26 MMAs (A*Whi + A*Wlo)
                #pragma unroll
                for (int n = 0; n < NT; n++) {
                    mma16(acc[n], aF[kc][0], aF[kc][1], aF[kc][2], aF[kc][3], wr[n][0], wr[n][1]);
                    mma16(acc[n], aF[kc][0], aF[kc][1], aF[kc][2], aF[kc][3], wr[n][2], wr[n][3]);
                }
            }
            {   // k8 tail
                u32t wt[NT][2];
                #pragma unroll
                for (int n = 0; n < NT; n++)
                    lds64u(wb + (u32t)((6 * 13 + n) * CHUNK), wt[n][0], wt[n][1]);
                #pragma unroll
                for (int n = 0; n < NT; n++) {
                    mma8(acc[n], aF[6][0], aF[6][1], wt[n][0]);
                    mma8(acc[n], aF[6][0], aF[6][1], wt[n][1]);
                }
            }

            if (l < 2) {
                // ===== hidden epilogue: A <- tanh(acc + bias), in registers =====
                const u32t bp = sb + OFF_BIAS + (u32t)(l * 416 + l4 * 8);
                #pragma unroll
                for (int n = 0; n < NT; n++) {
                    float bb0 = ldsf(bp + (u32t)(n * 32));
                    float bb1 = ldsf(bp + (u32t)(n * 32) + 4);
                    float v0 = tanh_fast(acc[n][0] + bb0);
                    float v1 = tanh_fast(acc[n][1] + bb1);
                    float v2 = tanh_fast(acc[n][2] + bb0);
                    float v3 = tanh_fast(acc[n][3] + bb1);
                    if (n == 12 && l4 >= 2) { v0 = v1 = v2 = v3 = 0.0f; }
                    int kc = n >> 1, f = (n & 1) * 2;
                    aF[kc][f]     = f16pack(v0, v1);
                    aF[kc][f + 1] = f16pack(v2, v3);
                }
            } else {
                // ===== Euler epilogue =====
                const float tn = (float)(s + 1) * dt;
                const u32t bp3 = sb + OFF_BIAS + (u32t)(2 * 416 + l4 * 8);
                #pragma unroll
                for (int n = 0; n < NT; n++) {
                    float v0, v1, v2, v3;
                    if (n < 12) {
                        int q0 = n * 8 + l4 * 2, q1 = q0 + 1;
                        float bb0 = ldsf(bp3 + (u32t)(n * 32));
                        float bb1 = ldsf(bp3 + (u32t)(n * 32) + 4);
                        float nz0 = __ldg(ps0 + q0 * CNUM);
                        float nz1 = __ldg(ps0 + q1 * CNUM);
                        float nz2 = __ldg(ps1 + q0 * CNUM);
                        float nz3 = __ldg(ps1 + q1 * CNUM);
                        float x0, x1, x2, x3;
                        lds64(xb0 + (u32t)(n * 32), x0, x1);
                        lds64(xb1 + (u32t)(n * 32), x2, x3);
                        v0 = fmaf((acc[n][0] + bb0) - nz0, dt, x0);
                        v1 = fmaf((acc[n][1] + bb1) - nz1, dt, x1);
                        v2 = fmaf((acc[n][2] + bb0) - nz2, dt, x2);
                        v3 = fmaf((acc[n][3] + bb1) - nz3, dt, x3);
                        sts64(xb0 + (u32t)(n * 32), v0, v1);
                        sts64(xb1 + (u32t)(n * 32), v2, v3);
                    } else {
                        if (l4 == 0) {
                            float bb0 = ldsf(bp3 + (u32t)(n * 32));
                            float nz0 = __ldg(pr0);
                            float nz2 = __ldg(pr1);
                            float x0 = ldsf(xb0 + (u32t)(n * 32));
                            float x2 = ldsf(xb1 + (u32t)(n * 32));
                            v0 = fmaf((acc[n][0] + bb0) - nz0, dt, x0);
                            v2 = fmaf((acc[n][2] + bb0) - nz2, dt, x2);
                            sts64(xb0 + (u32t)(n * 32), v0, tn);
                            sts64(xb1 + (u32t)(n * 32), v2, tn);
                            v1 = tn; v3 = tn;
                        } else {
                            v0 = v1 = v2 = v3 = 0.0f;
                        }
                    }
                    int kc = n >> 1, f = (n & 1) * 2;
                    aF[kc][f]     = f16pack(v0, v1);
                    aF[kc][f + 1] = f16pack(v2, v3);
                }
            }
        }
    }

    // ---- write result (B, 97, C) ----
    #pragma unroll
    for (int n = 0; n < NT; n++) {
        int q0 = n * 8 + l4 * 2, q1 = q0 + 1;
        float x0, x1, x2, x3;
        lds64(xb0 + (u32t)(n * 32), x0, x1);
        lds64(xb1 + (u32t)(n * 32), x2, x3);
        if (q0 < QP1) out[((size_t)gb0 * QP1 + q0) * CNUM + gc0] = x0;
        if (q1 < QP1) out[((size_t)gb0 * QP1 + q1) * CNUM + gc0] = x1;
        if (q0 < QP1) out[((size_t)gb1 * QP1 + q0) * CNUM + gc1] = x2;
        if (q1 < QP1) out[((size_t)gb1 * QP1 + q1) * CNUM + gc1] = x3;
    }
}

extern "C" void kernel_launch(void* const* d_in, const int* in_sizes, int n_in,
                              void* d_out, int out_size)
{
    const float* series     = (const float*)d_in[0];
    const float* rand_error = (const float*)d_in[1];
    const float* W1 = (const float*)d_in[2];
    const float* b1 = (const float*)d_in[3];
    const float* W2 = (const float*)d_in[4];
    const float* b2 = (const float*)d_in[5];
    const float* W3 = (const float*)d_in[6];
    const float* b3 = (const float*)d_in[7];
    float* out = (float*)d_out;

    cudaFuncSetAttribute(arima_mma_kernel,
                         cudaFuncAttributeMaxDynamicSharedMemorySize, SMEM_TOTAL);
    arima_mma_kernel<<<GRID, NTHREADS, SMEM_TOTAL>>>(
        series, rand_error, W1, b1, W2, b2, W3, b3, out);
}